// round 8
// baseline (speedup 1.0000x reference)
#include <cuda_runtime.h>
#include <cuda_fp16.h>

#define NVOX (128*128*128)
#define NBATCH 2
#define NTHREADS (NBATCH*NVOX)
#define INT_STEPS 7

// Max constant-offset spill past the last valid voxel: 16384+128+2 voxels.
// Tail-pad with zeros (static __device__ arrays are zero-initialized); spilled
// reads are always multiplied by an exact 0.0 weight (clip => frac == 0).
#define TAILPAD 16640

// fp32 state (exact accumulation), ping-pong
__device__ float2 g_zyA[NBATCH*NVOX + TAILPAD];
__device__ float2 g_zyB[NBATCH*NVOX + TAILPAD];
__device__ float  g_xA [NBATCH*NVOX + TAILPAD];
__device__ float  g_xB [NBATCH*NVOX + TAILPAD];
// fp16 gather mirror: half4 (z,y,x,0) packed as uint2 (8B aligned), ping-pong
__device__ uint2 g_mA[NBATCH*NVOX + TAILPAD];
__device__ uint2 g_mB[NBATCH*NVOX + TAILPAD];

__device__ __forceinline__ uint2 pack_h4(float z, float y, float x) {
    __half2 a = __floats2half2_rn(z, y);
    __half2 b = __floats2half2_rn(x, 0.0f);
    uint2 m;
    m.x = *(const unsigned int*)&a;
    m.y = *(const unsigned int*)&b;
    return m;
}

__device__ __forceinline__ float3 unpack_h4(uint2 m) {
    __half2 a = *(const __half2*)&m.x;
    __half2 b = *(const __half2*)&m.y;
    float2 zy = __half22float2(a);
    return make_float3(zy.x, zy.y, __half2float(__low2half(b)));
}

// ---------------------------------------------------------------------------
// v0 = vel/128, packed [b,z,y,x,3] -> fp32 state + half4 mirror
// ---------------------------------------------------------------------------
__global__ void __launch_bounds__(256)
scale_pack_kernel(const float* __restrict__ in,
                  float2* __restrict__ zy, float* __restrict__ xb,
                  uint2* __restrict__ m) {
    int i = blockIdx.x * blockDim.x + threadIdx.x;
    const float s = 1.0f / 128.0f;
    float v0 = in[i * 3 + 0] * s;
    float v1 = in[i * 3 + 1] * s;
    float v2 = in[i * 3 + 2] * s;
    zy[i] = make_float2(v0, v1);
    xb[i] = v2;
    m[i] = pack_h4(v0, v1, v2);
}

struct Coord {
    float wx, wy, wz;
    int o000;
};

__device__ __forceinline__ Coord make_coord(int x, int y, int z,
                                            float vz, float vy, float vx) {
    float lz = fminf(fmaxf((float)z + vz, 0.0f), 127.0f);
    float ly = fminf(fmaxf((float)y + vy, 0.0f), 127.0f);
    float lx = fminf(fmaxf((float)x + vx, 0.0f), 127.0f);
    float fz = floorf(lz), fy = floorf(ly), fx = floorf(lx);
    Coord c;
    c.wz = lz - fz; c.wy = ly - fy; c.wx = lx - fx;
    c.o000 = ((((int)fz << 7) + (int)fy) << 7) + (int)fx;
    return c;
}

// trilinear combine from 8 float3 corners
__device__ __forceinline__ float3 tri(float3 c000, float3 c001, float3 c010, float3 c011,
                                      float3 c100, float3 c101, float3 c110, float3 c111,
                                      float wx, float wy, float wz) {
    float a00x = fmaf(wx, c001.x - c000.x, c000.x);
    float a00y = fmaf(wx, c001.y - c000.y, c000.y);
    float a00z = fmaf(wx, c001.z - c000.z, c000.z);
    float a01x = fmaf(wx, c011.x - c010.x, c010.x);
    float a01y = fmaf(wx, c011.y - c010.y, c010.y);
    float a01z = fmaf(wx, c011.z - c010.z, c010.z);
    float a10x = fmaf(wx, c101.x - c100.x, c100.x);
    float a10y = fmaf(wx, c101.y - c100.y, c100.y);
    float a10z = fmaf(wx, c101.z - c100.z, c100.z);
    float a11x = fmaf(wx, c111.x - c110.x, c110.x);
    float a11y = fmaf(wx, c111.y - c110.y, c110.y);
    float a11z = fmaf(wx, c111.z - c110.z, c110.z);
    float b0x = fmaf(wy, a01x - a00x, a00x);
    float b0y = fmaf(wy, a01y - a00y, a00y);
    float b0z = fmaf(wy, a01z - a00z, a00z);
    float b1x = fmaf(wy, a11x - a10x, a10x);
    float b1y = fmaf(wy, a11y - a10y, a10y);
    float b1z = fmaf(wy, a11z - a10z, a10z);
    return make_float3(fmaf(wz, b1x - b0x, b0x),
                       fmaf(wz, b1y - b0y, b0y),
                       fmaf(wz, b1z - b0z, b0z));
}

// ---------------------------------------------------------------------------
// One step, two x-adjacent voxels per thread with predicated corner sharing.
// ---------------------------------------------------------------------------
template<bool FINAL>
__global__ void __launch_bounds__(256)
step_kernel(const float2* __restrict__ src_zy, const float* __restrict__ src_x,
            const uint2* __restrict__ msrc,
            float2* __restrict__ dst_zy, float* __restrict__ dst_x,
            uint2* __restrict__ mdst,
            float* __restrict__ out) {
    int t = blockIdx.x * blockDim.x + threadIdx.x;     // 0..NTHREADS/2-1
    int idx0 = t * 2;
    int x0 = idx0 & 127;
    int y  = (idx0 >> 7) & 127;
    int z  = (idx0 >> 14) & 127;
    int b  = idx0 >> 21;
    int vox0 = idx0 & (NVOX - 1);

    // own state: vectorized pair loads
    float4 szy = __ldg((const float4*)(src_zy + b * NVOX + vox0));
    float2 sx  = __ldg((const float2*)(src_x  + b * NVOX + vox0));

    Coord cA = make_coord(x0,     y, z, szy.x, szy.y, sx.x);
    Coord cB = make_coord(x0 + 1, y, z, szy.z, szy.w, sx.y);

    bool coh = (cB.o000 == cA.o000 + 1);

    const uint2* g = msrc + b * NVOX;
    const uint2* gA = g + cA.o000;
    const uint2* gB = g + cB.o000;

    const int R[4] = {0, 128, 16384, 16512};

    float3 A0[4], A1[4];   // voxel A corners per row (r0, r1)
    float3 B0[4], B1[4];   // voxel B
    #pragma unroll
    for (int r = 0; r < 4; r++) {
        uint2 a0 = __ldg(gA + R[r]);
        uint2 a1 = __ldg(gA + R[r] + 1);
        // B row start: shared with A's r1 when coherent, else its own load
        uint2 b0;
        if (coh) b0 = a1;
        else     b0 = __ldg(gB + R[r]);
        // B row +1: coh ? A base + 2 : B base + 1   (single always-on load)
        const uint2* pb1 = coh ? (gA + R[r] + 2) : (gB + R[r] + 1);
        uint2 b1 = __ldg(pb1);
        A0[r] = unpack_h4(a0);
        A1[r] = unpack_h4(a1);
        B0[r] = unpack_h4(b0);
        B1[r] = unpack_h4(b1);
    }

    float3 rA = tri(A0[0], A1[0], A0[1], A1[1], A0[2], A1[2], A0[3], A1[3],
                    cA.wx, cA.wy, cA.wz);
    float3 rB = tri(B0[0], B1[0], B0[1], B1[1], B0[2], B1[2], B0[3], B1[3],
                    cB.wx, cB.wy, cB.wz);

    float az = szy.x + rA.x, ay = szy.y + rA.y, ax = sx.x + rA.z;
    float bz = szy.z + rB.x, by = szy.w + rB.y, bx = sx.y + rB.z;

    if (FINAL) {
        float2* o = (float2*)(out + (size_t)idx0 * 3);
        o[0] = make_float2(az, ay);
        o[1] = make_float2(ax, bz);
        o[2] = make_float2(by, bx);
    } else {
        int d = b * NVOX + vox0;
        *(float4*)(dst_zy + d) = make_float4(az, ay, bz, by);
        *(float2*)(dst_x + d)  = make_float2(ax, bx);
        uint2 mA2 = pack_h4(az, ay, ax);
        uint2 mB2 = pack_h4(bz, by, bx);
        *(uint4*)(mdst + d) = make_uint4(mA2.x, mA2.y, mB2.x, mB2.y);
    }
}

// ---------------------------------------------------------------------------
extern "C" void kernel_launch(void* const* d_in, const int* in_sizes, int n_in,
                              void* d_out, int out_size) {
    const float* vel = (const float*)d_in[0];
    float* out = (float*)d_out;

    float2 *zyA, *zyB; float *xA, *xB; uint2 *mA, *mB;
    cudaGetSymbolAddress((void**)&zyA, g_zyA);
    cudaGetSymbolAddress((void**)&zyB, g_zyB);
    cudaGetSymbolAddress((void**)&xA,  g_xA);
    cudaGetSymbolAddress((void**)&xB,  g_xB);
    cudaGetSymbolAddress((void**)&mA,  g_mA);
    cudaGetSymbolAddress((void**)&mB,  g_mB);

    scale_pack_kernel<<<NTHREADS / 256, 256>>>(vel, zyA, xA, mA);

    const int nblocks = (NTHREADS / 2) / 256;
    const float2* szy = zyA; const float* sx = xA; const uint2* ms = mA;
    float2* dzy = zyB; float* dx = xB; uint2* md = mB;

    for (int s = 0; s < INT_STEPS - 1; s++) {
        step_kernel<false><<<nblocks, 256>>>(szy, sx, ms, dzy, dx, md, nullptr);
        { const float2* t = dzy; dzy = (float2*)szy; szy = t; }
        { const float*  t = dx;  dx  = (float*)sx;   sx  = t; }
        { const uint2*  t = md;  md  = (uint2*)ms;   ms  = t; }
    }
    step_kernel<true><<<nblocks, 256>>>(szy, sx, ms, nullptr, nullptr, nullptr, out);
}

// round 9
// speedup vs baseline: 1.5275x; 1.5275x over previous
#include <cuda_runtime.h>
#include <cuda_fp16.h>

#define NVOX (128*128*128)
#define NBATCH 2
#define NTHREADS (NBATCH*NVOX)
#define INT_STEPS 7

// Max constant-offset spill past the last valid voxel: 16384+128+1 voxels.
// Tail-pad with zeros (static __device__ arrays are zero-initialized); spilled
// reads are always multiplied by an exact 0.0 weight (clip => frac == 0).
#define TAILPAD 16640

// State: half4 (z,y,x,0) packed as uint2 (8B), ping-pong. fp32 math in-register.
__device__ uint2 g_mA[NBATCH*NVOX + TAILPAD];
__device__ uint2 g_mB[NBATCH*NVOX + TAILPAD];

__device__ __forceinline__ uint2 pack_h4(float z, float y, float x) {
    __half2 a = __floats2half2_rn(z, y);
    __half2 b = __floats2half2_rn(x, 0.0f);
    uint2 m;
    m.x = *(const unsigned int*)&a;
    m.y = *(const unsigned int*)&b;
    return m;
}

__device__ __forceinline__ float3 unpack_h4(uint2 m) {
    __half2 a = *(const __half2*)&m.x;
    __half2 b = *(const __half2*)&m.y;
    float2 zy = __half22float2(a);
    return make_float3(zy.x, zy.y, __half2float(__low2half(b)));
}

// ---------------------------------------------------------------------------
// v0 = vel/128, packed [b,z,y,x,3] -> half4 state
// ---------------------------------------------------------------------------
__global__ void __launch_bounds__(256)
scale_pack_kernel(const float* __restrict__ in, uint2* __restrict__ m) {
    int i = blockIdx.x * blockDim.x + threadIdx.x;
    const float s = 1.0f / 128.0f;
    float v0 = in[i * 3 + 0] * s;
    float v1 = in[i * 3 + 1] * s;
    float v2 = in[i * 3 + 2] * s;
    m[i] = pack_h4(v0, v1, v2);
}

// ---------------------------------------------------------------------------
// Trilinear over 8 corners at compile-time constant offsets; one LDG.64 per
// corner fetches all 3 channels.
// ---------------------------------------------------------------------------
__device__ __forceinline__ float3 gather_lerp(const uint2* __restrict__ g,
                                              float wx, float wy, float wz) {
    float3 c000 = unpack_h4(__ldg(g + 0));
    float3 c001 = unpack_h4(__ldg(g + 1));
    float3 c010 = unpack_h4(__ldg(g + 128));
    float3 c011 = unpack_h4(__ldg(g + 129));
    float3 c100 = unpack_h4(__ldg(g + 16384));
    float3 c101 = unpack_h4(__ldg(g + 16385));
    float3 c110 = unpack_h4(__ldg(g + 16512));
    float3 c111 = unpack_h4(__ldg(g + 16513));

    float a00x = fmaf(wx, c001.x - c000.x, c000.x);
    float a00y = fmaf(wx, c001.y - c000.y, c000.y);
    float a00z = fmaf(wx, c001.z - c000.z, c000.z);
    float a01x = fmaf(wx, c011.x - c010.x, c010.x);
    float a01y = fmaf(wx, c011.y - c010.y, c010.y);
    float a01z = fmaf(wx, c011.z - c010.z, c010.z);
    float a10x = fmaf(wx, c101.x - c100.x, c100.x);
    float a10y = fmaf(wx, c101.y - c100.y, c100.y);
    float a10z = fmaf(wx, c101.z - c100.z, c100.z);
    float a11x = fmaf(wx, c111.x - c110.x, c110.x);
    float a11y = fmaf(wx, c111.y - c110.y, c110.y);
    float a11z = fmaf(wx, c111.z - c110.z, c110.z);

    float b0x = fmaf(wy, a01x - a00x, a00x);
    float b0y = fmaf(wy, a01y - a00y, a00y);
    float b0z = fmaf(wy, a01z - a00z, a00z);
    float b1x = fmaf(wy, a11x - a10x, a10x);
    float b1y = fmaf(wy, a11y - a10y, a10y);
    float b1z = fmaf(wy, a11z - a10z, a10z);

    return make_float3(fmaf(wz, b1x - b0x, b0x),
                       fmaf(wz, b1y - b0y, b0y),
                       fmaf(wz, b1z - b0z, b0z));
}

// ---------------------------------------------------------------------------
// One step: v <- v + trilerp(v, grid + v), state entirely in half4.
// ---------------------------------------------------------------------------
template<bool FINAL>
__global__ void __launch_bounds__(256)
step_kernel(const uint2* __restrict__ msrc, uint2* __restrict__ mdst,
            float* __restrict__ out) {
    int idx = blockIdx.x * blockDim.x + threadIdx.x;   // 0..NTHREADS-1
    int x = idx & 127;
    int y = (idx >> 7) & 127;
    int z = (idx >> 14) & 127;
    int b = idx >> 21;
    int vox = idx & (NVOX - 1);

    const uint2* mb = msrc + b * NVOX;
    float3 v = unpack_h4(__ldg(mb + vox));

    float lz = fminf(fmaxf((float)z + v.x, 0.0f), 127.0f);
    float ly = fminf(fmaxf((float)y + v.y, 0.0f), 127.0f);
    float lx = fminf(fmaxf((float)x + v.z, 0.0f), 127.0f);

    float fz = floorf(lz), fy = floorf(ly), fx = floorf(lx);
    float wz = lz - fz, wy = ly - fy, wx = lx - fx;
    // i1 clamp elided: when i0 == 127 the weight is exactly 0 and the
    // +1/+128/+16384 spill reads finite in-buffer or zero-pad data.
    int o000 = ((((int)fz << 7) + (int)fy) << 7) + (int)fx;

    float3 r = gather_lerp(mb + o000, wx, wy, wz);

    float resz = v.x + r.x;
    float resy = v.y + r.y;
    float resx = v.z + r.z;

    if (FINAL) {
        float* o = out + (size_t)idx * 3;
        o[0] = resz; o[1] = resy; o[2] = resx;
    } else {
        mdst[b * NVOX + vox] = pack_h4(resz, resy, resx);
    }
}

// ---------------------------------------------------------------------------
extern "C" void kernel_launch(void* const* d_in, const int* in_sizes, int n_in,
                              void* d_out, int out_size) {
    const float* vel = (const float*)d_in[0];
    float* out = (float*)d_out;

    uint2 *mA, *mB;
    cudaGetSymbolAddress((void**)&mA, g_mA);
    cudaGetSymbolAddress((void**)&mB, g_mB);

    const int nblocks = NTHREADS / 256;

    scale_pack_kernel<<<nblocks, 256>>>(vel, mA);

    const uint2* ms = mA;
    uint2* md = mB;
    for (int s = 0; s < INT_STEPS - 1; s++) {
        step_kernel<false><<<nblocks, 256>>>(ms, md, nullptr);
        const uint2* t = md;
        md = (uint2*)ms;
        ms = t;
    }
    step_kernel<true><<<nblocks, 256>>>(ms, nullptr, out);
}